// round 16
// baseline (speedup 1.0000x reference)
#include <cuda_runtime.h>
#include <cuda_fp16.h>
#include <cstdint>

// ---------------- problem constants ----------------
#define N_TOK 4096
#define IN_F  4096
#define OUT_F 4096
#define N_BLK 8192
#define IN_B  128          // IN_FEATURES / 32
#define NBR   8            // block-rows per CTA -> 256 output cols
#define GCOLS 256
#define MT    64           // token tile
#define NCONS 8            // consumer warps (4 wsub x 2 halves)
#define NTHR  320          // 8 consumer warps + 2 producer warps
#define PWID  8            // first producer warp id

// ---------------- smem layout (bytes) ----------------
#define OFF_NU     0
#define OFF_MBF    8        // full mbarriers, 4 x 8B
#define OFF_MBE    40       // empty mbarriers, 4 x 8B
#define OFF_ROWOFF 72       // 9 ints
#define OFF_CNT    128      // 256 ints (key = bc*2 + half)
#define OFF_UBC    1152     // 128 u32
#define OFF_BIAS   1664     // 256 floats
#define OFF_ENT    2688     // up to 1024 u32
#define OFF_STG    6784     // 4 pipeline stages
#define X_SZ       5120     // 64 rows * 80B
#define WBLK       2560     // 32 rows * 80B
#define STAGE      25600    // x + 8 weight blocks
#define NSTG       4
#define SMEM_TOTAL (OFF_STG + NSTG * STAGE)   // 109184 -> 2 CTAs/SM

// fp16 copies of x and weights (alloc-free rule -> device globals)
__device__ __half g_xh[(size_t)N_TOK * IN_F];
__device__ __half g_wh[(size_t)N_BLK * 1024];

// ---------------- helpers ----------------
static __device__ __forceinline__ uint32_t smem_u32(const void* p) {
    uint32_t a;
    asm("{ .reg .u64 t; cvta.to.shared.u64 t, %1; cvt.u32.u64 %0, t; }" : "=r"(a) : "l"(p));
    return a;
}
static __device__ __forceinline__ void cp16(uint32_t dst, const void* src) {
    asm volatile("cp.async.cg.shared.global [%0], [%1], 16;" :: "r"(dst), "l"(src));
}
#define CP_COMMIT() asm volatile("cp.async.commit_group;" ::: "memory")
#define CP_WAIT(n)  asm volatile("cp.async.wait_group %0;" :: "n"(n) : "memory")

#define MBARRIER_INIT(addr, cnt) \
    asm volatile("mbarrier.init.shared.b64 [%0], %1;" :: "r"((uint32_t)(addr)), "r"((uint32_t)(cnt)) : "memory")
#define MBARRIER_ARRIVE(addr) \
    asm volatile("mbarrier.arrive.shared.b64 _, [%0];" :: "r"((uint32_t)(addr)) : "memory")

#define MBARRIER_WAIT_PARITY(mbar_smem_addr, phase_parity) do { \
    uint32_t _mbar = (uint32_t)(mbar_smem_addr); \
    uint32_t _parity = (uint32_t)(phase_parity); \
    uint32_t _done; \
    asm volatile( \
        "{\n\t" \
        ".reg .pred p;\n\t" \
        "mbarrier.try_wait.parity.acquire.cta.shared::cta.b64 p, [%1], %2;\n\t" \
        "selp.b32 %0, 1, 0, p;\n\t" \
        "}" \
        : "=r"(_done) : "r"(_mbar), "r"(_parity) : "memory"); \
    if (!_done) { \
        asm volatile( \
            "{\n\t" \
            ".reg .pred P1;\n\t" \
            "WAIT_LOOP_%=:\n\t" \
            "mbarrier.try_wait.parity.acquire.cta.shared::cta.b64 P1, [%0], %1, 0x989680;\n\t" \
            "@P1 bra.uni WAIT_DONE_%=;\n\t" \
            "bra.uni WAIT_LOOP_%=;\n\t" \
            "WAIT_DONE_%=:\n\t" \
            "}" \
            :: "r"(_mbar), "r"(_parity) : "memory"); \
    } \
} while(0)

#define LDSM4(R0,R1,R2,R3,ADDR) \
    asm volatile("ldmatrix.sync.aligned.m8n8.x4.shared.b16 {%0,%1,%2,%3}, [%4];" \
        : "=r"(R0), "=r"(R1), "=r"(R2), "=r"(R3) : "r"(ADDR))

static __device__ __forceinline__ void mmaf16(float (&d)[4], const uint32_t (&a)[4],
                                              uint32_t b0, uint32_t b1) {
    asm volatile(
        "mma.sync.aligned.m16n8k16.row.col.f32.f16.f16.f32 "
        "{%0,%1,%2,%3}, {%4,%5,%6,%7}, {%8,%9}, {%0,%1,%2,%3};"
        : "+f"(d[0]), "+f"(d[1]), "+f"(d[2]), "+f"(d[3])
        : "r"(a[0]), "r"(a[1]), "r"(a[2]), "r"(a[3]), "r"(b0), "r"(b1));
}

static __device__ __forceinline__ int lb(const int* __restrict__ a, int n, int v) {
    int lo = 0, hi = n;
    while (lo < hi) { int m = (lo + hi) >> 1; if (a[m] < v) lo = m + 1; else hi = m; }
    return lo;
}

// One 32x32 weight block vs this warp's 16-token A fragments.
// All 4 LDSM4 issued up front so their latencies overlap; then 8 mma.
template<int J>
static __device__ __forceinline__ void do_block(float (&acc)[16][4],
                                                const uint32_t (&A)[2][4],
                                                uint32_t base) {
    uint32_t B[4][4];
    LDSM4(B[0][0], B[0][1], B[0][2], B[0][3], base);                 // p0 ks0
    LDSM4(B[1][0], B[1][1], B[1][2], B[1][3], base + 32);            // p0 ks1
    LDSM4(B[2][0], B[2][1], B[2][2], B[2][3], base + 1280);          // p1 ks0
    LDSM4(B[3][0], B[3][1], B[3][2], B[3][3], base + 1312);          // p1 ks1
    mmaf16(acc[J * 4 + 0], A[0], B[0][0], B[0][1]);
    mmaf16(acc[J * 4 + 1], A[0], B[0][2], B[0][3]);
    mmaf16(acc[J * 4 + 0], A[1], B[1][0], B[1][1]);
    mmaf16(acc[J * 4 + 1], A[1], B[1][2], B[1][3]);
    mmaf16(acc[J * 4 + 2], A[0], B[2][0], B[2][1]);
    mmaf16(acc[J * 4 + 3], A[0], B[2][2], B[2][3]);
    mmaf16(acc[J * 4 + 2], A[1], B[3][0], B[3][1]);
    mmaf16(acc[J * 4 + 3], A[1], B[3][2], B[3][3]);
}

// ---------------- pre-pass: fp32 -> fp16 (x and w fused) ----------------
__global__ void cvt_f16_all(const float4* __restrict__ xs, uint2* __restrict__ xd,
                            const float4* __restrict__ ws, uint2* __restrict__ wd,
                            int nx4, int ntot4) {
    for (int i = blockIdx.x * blockDim.x + threadIdx.x; i < ntot4; i += gridDim.x * blockDim.x) {
        bool isx = i < nx4;
        float4 v = isx ? xs[i] : ws[i - nx4];
        __half2 h0 = __floats2half2_rn(v.x, v.y);
        __half2 h1 = __floats2half2_rn(v.z, v.w);
        uint2 o;
        o.x = *reinterpret_cast<uint32_t*>(&h0);
        o.y = *reinterpret_cast<uint32_t*>(&h1);
        if (isx) xd[i] = o; else wd[i - nx4] = o;
    }
}

// ---------------- main block-sparse GEMM ----------------
__global__ void __launch_bounds__(NTHR, 2)
bsl_main(const float* __restrict__ bias,
         const int* __restrict__ block_ids,
         float* __restrict__ out)
{
    extern __shared__ __align__(1024) char smem[];
    const uint32_t sb = smem_u32(smem);
    const int tid  = threadIdx.x;
    const int wid  = tid >> 5;
    const int lane = tid & 31;
    const int wsub = wid & 3;         // consumer: token subtile (16 rows)
    const int h    = (wid >> 2) & 1;  // consumer: column half (4 block-rows)
    const int m0   = blockIdx.x * MT;
    const int brg  = blockIdx.y;      // 8-block-row group (0..15)

    int*      row_off = (int*)(smem + OFF_ROWOFF);
    int*      cnt     = (int*)(smem + OFF_CNT);
    uint32_t* ubc     = (uint32_t*)(smem + OFF_UBC);
    float*    bias_s  = (float*)(smem + OFF_BIAS);
    uint32_t* ents    = (uint32_t*)(smem + OFF_ENT);

    // ---- planning + mbarrier init ----
    if (tid < 9) row_off[tid] = lb(block_ids, N_BLK, (brg * NBR + tid) * IN_B);
    if (tid >= 16 && tid < 272) cnt[tid - 16] = 0;
    if (tid < GCOLS) bias_s[tid] = bias[brg * GCOLS + tid];
    if (tid == 0) {
        #pragma unroll
        for (int s = 0; s < NSTG; s++) {
            MBARRIER_INIT(sb + OFF_MBF + 8 * s, 32);    // full: 32 lanes of owner producer
            MBARRIER_INIT(sb + OFF_MBE + 8 * s, NCONS); // empty: 8 consumer warps
        }
    }
    __syncthreads();

    const int e0  = row_off[0];
    const int tot = row_off[NBR] - e0;

    for (int t = tid; t < tot; t += NTHR) {
        int flat = block_ids[e0 + t];
        int key = ((flat & 127) << 1) | (((flat >> 7) - brg * NBR) >> 2);
        atomicAdd(&cnt[key], 1);
    }
    __syncthreads();

    if (tid == 0) {
        int acc = 0, nuv = 0;
        for (int c = 0; c < 128; c++) {
            int c0 = cnt[2 * c], c1 = cnt[2 * c + 1];
            if (c0 + c1) ubc[nuv++] = ((uint32_t)c << 24) | ((uint32_t)acc << 8)
                                    | ((uint32_t)c0 << 4) | (uint32_t)c1;
            cnt[2 * c] = acc;
            cnt[2 * c + 1] = acc + c0;
            acc += c0 + c1;
        }
        *(int*)(smem + OFF_NU) = nuv;
    }
    __syncthreads();

    for (int t = tid; t < tot; t += NTHR) {
        int flat = block_ids[e0 + t];
        int bc   = flat & 127;
        int brl  = (flat >> 7) - brg * NBR;          // 0..7
        int pos  = atomicAdd(&cnt[(bc << 1) | (brl >> 2)], 1);
        ents[pos] = ((uint32_t)(e0 + t) << 8) | (uint32_t)brl;
    }
    __syncthreads();

    const int nu = *(int*)(smem + OFF_NU);

    if (wid >= PWID) {
        // ================= producer warps (2) =================
        const int pw = wid - PWID;    // 0 -> even iterations, 1 -> odd
        const __half*  x_src_lane = g_xh + (size_t)(m0 + (lane >> 2)) * IN_F + (lane & 3) * 8;
        const uint32_t x_dst_lane = (uint32_t)((lane >> 2) * 80 + (lane & 3) * 16);
        const uint32_t w_src_lane = (uint32_t)((lane >> 2) * 32 + (lane & 3) * 8);
        const uint32_t w_dst_lane = (uint32_t)((lane >> 2) * 80 + (lane & 3) * 16);

        int last = -1;
        for (int it = pw; it < nu; it += 2) {
            int s = it & 3;
            if (it >= 4) MBARRIER_WAIT_PARITY(sb + OFF_MBE + 8 * s, ((it >> 2) - 1) & 1);

            uint32_t u = ubc[it];
            int bc  = (int)(u >> 24);
            int st  = (int)((u >> 8) & 0xFFFF);
            int cct = (int)((u >> 4) & 15) + (int)(u & 15);
            uint32_t base = sb + OFF_STG + (uint32_t)s * STAGE;
            const __half* xs = x_src_lane + bc * 32;
            #pragma unroll
            for (int q = 0; q < 8; q++)
                cp16(base + x_dst_lane + (uint32_t)(q * 640), xs + (size_t)q * 8 * IN_F);
            uint32_t wbase = base + X_SZ;
            for (int e = 0; e < cct; e++) {
                const __half* wsrc = g_wh + (size_t)(ents[st + e] >> 8) * 1024 + w_src_lane;
                uint32_t wdst = wbase + (uint32_t)e * WBLK + w_dst_lane;
                #pragma unroll
                for (int kk = 0; kk < 4; kk++)
                    cp16(wdst + (uint32_t)(kk * 640), wsrc + kk * 256);
            }
            CP_COMMIT();

            // own chain: CP_WAIT(1) -> my previous group (iteration it-2) landed
            if (it >= 2) {
                CP_WAIT(1);
                MBARRIER_ARRIVE(sb + OFF_MBF + 8 * ((it - 2) & 3));
            }
            last = it;
        }
        if (last >= 0) {
            CP_WAIT(0);
            MBARRIER_ARRIVE(sb + OFF_MBF + 8 * (last & 3));
        }
    } else {
        // ================= consumer warps =================
        const int jj = lane >> 3, rr = lane & 7;
        const uint32_t a_off = (uint32_t)((wsub * 16 + (jj & 1) * 8 + rr) * 80 + (jj >> 1) * 16);
        const uint32_t b_off = (uint32_t)(((jj >> 1) * 8 + rr) * 80 + (jj & 1) * 16);

        float acc[16][4];
        #pragma unroll
        for (int nt = 0; nt < 16; nt++)
            #pragma unroll
            for (int q = 0; q < 4; q++) acc[nt][q] = 0.0f;

        for (int i = 0; i < nu; i++) {
            int s = i & 3, k = i >> 2;

            // decode BEFORE the wait (ubc/ents are frozen after planning)
            uint32_t u = ubc[i];
            int st  = (int)((u >> 8) & 0xFFFF);
            int cc0 = (int)((u >> 4) & 15);
            int myst = st + (h ? cc0 : 0);
            int mycc = h ? (int)(u & 15) : cc0;

            if (mycc) {
                MBARRIER_WAIT_PARITY(sb + OFF_MBF + 8 * s, k & 1);
                uint32_t stg = sb + OFF_STG + (uint32_t)s * STAGE;
                uint32_t A[2][4];
                LDSM4(A[0][0], A[0][1], A[0][2], A[0][3], stg + a_off);
                LDSM4(A[1][0], A[1][1], A[1][2], A[1][3], stg + a_off + 32);
                uint32_t wslot0 = stg + X_SZ + (uint32_t)(myst - st) * WBLK + b_off;
                for (int e = 0; e < mycc; e++) {
                    uint32_t en = ents[myst + e];
                    uint32_t base = wslot0 + (uint32_t)e * WBLK;
                    switch (en & 3) {
                        case 0: do_block<0>(acc, A, base); break;
                        case 1: do_block<1>(acc, A, base); break;
                        case 2: do_block<2>(acc, A, base); break;
                        default: do_block<3>(acc, A, base); break;
                    }
                }
                __syncwarp();
            }
            // arrive empty regardless (skip-wait on empty iterations is safe:
            // we never touch the stage, so ordering vs producer refill holds)
            if (lane == 0) MBARRIER_ARRIVE(sb + OFF_MBE + 8 * s);
        }

        // ---- epilogue ----
        const int r4 = lane >> 2, c2 = (lane & 3) * 2;
        const int row = m0 + wsub * 16 + r4;
        const float* bs = bias_s + h * 128;
        #pragma unroll
        for (int nt = 0; nt < 16; nt++) {
            int lc = nt * 8 + c2;
            float b0 = bs[lc], b1 = bs[lc + 1];
            float* p = out + (size_t)row * OUT_F + brg * GCOLS + h * 128 + lc;
            float2 v0 = { acc[nt][0] + b0, acc[nt][1] + b1 };
            float2 v1 = { acc[nt][2] + b0, acc[nt][3] + b1 };
            *(float2*)p = v0;
            *(float2*)(p + 8 * OUT_F) = v1;
        }
    }
}

// ---------------- launch ----------------
extern "C" void kernel_launch(void* const* d_in, const int* in_sizes, int n_in,
                              void* d_out, int out_size)
{
    const float* x    = (const float*)d_in[0];   // [4096,4096] f32
    const float* w    = (const float*)d_in[1];   // [8192,32,32] f32
    const float* bias = (const float*)d_in[2];   // [4096] f32
    const int*   bids = (const int*)d_in[3];     // [8192] i32 sorted flat ids
    float* out = (float*)d_out;

    void* px = nullptr; void* pw = nullptr;
    cudaGetSymbolAddress(&px, g_xh);
    cudaGetSymbolAddress(&pw, g_wh);

    const int nx4 = (N_TOK * IN_F) / 4;
    const int nw4 = (N_BLK * 1024) / 4;
    cvt_f16_all<<<4096, 256>>>((const float4*)x, (uint2*)px,
                               (const float4*)w, (uint2*)pw, nx4, nx4 + nw4);

    cudaFuncSetAttribute(bsl_main, cudaFuncAttributeMaxDynamicSharedMemorySize, SMEM_TOTAL);
    bsl_main<<<dim3(64, 16), NTHR, SMEM_TOTAL>>>(bias, bids, out);

    (void)in_sizes; (void)n_in; (void)out_size;
}

// round 17
// speedup vs baseline: 1.1184x; 1.1184x over previous
#include <cuda_runtime.h>
#include <cuda_fp16.h>
#include <cstdint>

// ---------------- problem constants ----------------
#define N_TOK 4096
#define IN_F  4096
#define OUT_F 4096
#define N_BLK 8192
#define IN_B  128          // IN_FEATURES / 32
#define NBR   8            // block-rows per CTA -> 256 output cols
#define GCOLS 256
#define MT    64           // token tile
#define NCONS 8            // consumer warps (4 wsub x 2 halves)
#define NTHR  320          // 8 consumer warps + 2 producer warps
#define PWID  8            // first producer warp id

// ---------------- smem layout (bytes) ----------------
#define OFF_NU     0
#define OFF_MBF    8        // full mbarriers, 4 x 8B
#define OFF_MBE    40       // empty mbarriers, 4 x 8B
#define OFF_ROWOFF 72       // 9 ints
#define OFF_CNT    128      // 256 ints (key = bc*2 + half)
#define OFF_UBC    1152     // 128 u32
#define OFF_BIAS   1664     // 256 floats
#define OFF_ENT    2688     // up to 1024 u32
#define OFF_STG    6784     // 4 pipeline stages
#define X_SZ       5120     // 64 rows * 80B
#define WBLK       2560     // 32 rows * 80B
#define STAGE      25600    // x + 8 weight blocks
#define NSTG       4
#define SMEM_TOTAL (OFF_STG + NSTG * STAGE)   // 109184 -> 2 CTAs/SM

// fp16 copies of x and weights (alloc-free rule -> device globals)
__device__ __half g_xh[(size_t)N_TOK * IN_F];
__device__ __half g_wh[(size_t)N_BLK * 1024];

// ---------------- helpers ----------------
static __device__ __forceinline__ uint32_t smem_u32(const void* p) {
    uint32_t a;
    asm("{ .reg .u64 t; cvta.to.shared.u64 t, %1; cvt.u32.u64 %0, t; }" : "=r"(a) : "l"(p));
    return a;
}
static __device__ __forceinline__ void cp16(uint32_t dst, const void* src) {
    asm volatile("cp.async.cg.shared.global [%0], [%1], 16;" :: "r"(dst), "l"(src));
}
#define CP_COMMIT() asm volatile("cp.async.commit_group;" ::: "memory")
#define CP_WAIT(n)  asm volatile("cp.async.wait_group %0;" :: "n"(n) : "memory")

#define MBARRIER_INIT(addr, cnt) \
    asm volatile("mbarrier.init.shared.b64 [%0], %1;" :: "r"((uint32_t)(addr)), "r"((uint32_t)(cnt)) : "memory")
#define MBARRIER_ARRIVE(addr) \
    asm volatile("mbarrier.arrive.shared.b64 _, [%0];" :: "r"((uint32_t)(addr)) : "memory")

#define MBARRIER_WAIT_PARITY(mbar_smem_addr, phase_parity) do { \
    uint32_t _mbar = (uint32_t)(mbar_smem_addr); \
    uint32_t _parity = (uint32_t)(phase_parity); \
    uint32_t _done; \
    asm volatile( \
        "{\n\t" \
        ".reg .pred p;\n\t" \
        "mbarrier.try_wait.parity.acquire.cta.shared::cta.b64 p, [%1], %2;\n\t" \
        "selp.b32 %0, 1, 0, p;\n\t" \
        "}" \
        : "=r"(_done) : "r"(_mbar), "r"(_parity) : "memory"); \
    if (!_done) { \
        asm volatile( \
            "{\n\t" \
            ".reg .pred P1;\n\t" \
            "WAIT_LOOP_%=:\n\t" \
            "mbarrier.try_wait.parity.acquire.cta.shared::cta.b64 P1, [%0], %1, 0x989680;\n\t" \
            "@P1 bra.uni WAIT_DONE_%=;\n\t" \
            "bra.uni WAIT_LOOP_%=;\n\t" \
            "WAIT_DONE_%=:\n\t" \
            "}" \
            :: "r"(_mbar), "r"(_parity) : "memory"); \
    } \
} while(0)

#define LDSM4(R0,R1,R2,R3,ADDR) \
    asm volatile("ldmatrix.sync.aligned.m8n8.x4.shared.b16 {%0,%1,%2,%3}, [%4];" \
        : "=r"(R0), "=r"(R1), "=r"(R2), "=r"(R3) : "r"(ADDR))

static __device__ __forceinline__ void mmaf16(float (&d)[4], const uint32_t (&a)[4],
                                              uint32_t b0, uint32_t b1) {
    asm volatile(
        "mma.sync.aligned.m16n8k16.row.col.f32.f16.f16.f32 "
        "{%0,%1,%2,%3}, {%4,%5,%6,%7}, {%8,%9}, {%0,%1,%2,%3};"
        : "+f"(d[0]), "+f"(d[1]), "+f"(d[2]), "+f"(d[3])
        : "r"(a[0]), "r"(a[1]), "r"(a[2]), "r"(a[3]), "r"(b0), "r"(b1));
}

static __device__ __forceinline__ int lb(const int* __restrict__ a, int n, int v) {
    int lo = 0, hi = n;
    while (lo < hi) { int m = (lo + hi) >> 1; if (a[m] < v) lo = m + 1; else hi = m; }
    return lo;
}

// One 32x32 weight block vs this warp's 16-token A fragments.
// (R15 interleaved form — lowest live-register footprint, no ALU bloat)
template<int J>
static __device__ __forceinline__ void do_block(float (&acc)[16][4],
                                                const uint32_t (&A)[2][4],
                                                uint32_t base) {
    #pragma unroll
    for (int p = 0; p < 2; p++) {
        #pragma unroll
        for (int ks = 0; ks < 2; ks++) {
            uint32_t b0, b1, b2, b3;
            LDSM4(b0, b1, b2, b3, base + (uint32_t)(p * 1280 + ks * 32));
            mmaf16(acc[J * 4 + p * 2 + 0], A[ks], b0, b1);
            mmaf16(acc[J * 4 + p * 2 + 1], A[ks], b2, b3);
        }
    }
}

// ---------------- pre-pass: fp32 -> fp16 (x and w fused) ----------------
__global__ void cvt_f16_all(const float4* __restrict__ xs, uint2* __restrict__ xd,
                            const float4* __restrict__ ws, uint2* __restrict__ wd,
                            int nx4, int ntot4) {
    for (int i = blockIdx.x * blockDim.x + threadIdx.x; i < ntot4; i += gridDim.x * blockDim.x) {
        bool isx = i < nx4;
        float4 v = isx ? xs[i] : ws[i - nx4];
        __half2 h0 = __floats2half2_rn(v.x, v.y);
        __half2 h1 = __floats2half2_rn(v.z, v.w);
        uint2 o;
        o.x = *reinterpret_cast<uint32_t*>(&h0);
        o.y = *reinterpret_cast<uint32_t*>(&h1);
        if (isx) xd[i] = o; else wd[i - nx4] = o;
    }
}

// ---------------- main block-sparse GEMM ----------------
__global__ void __launch_bounds__(NTHR, 2)
bsl_main(const float* __restrict__ bias,
         const int* __restrict__ block_ids,
         float* __restrict__ out)
{
    extern __shared__ __align__(1024) char smem[];
    const uint32_t sb = smem_u32(smem);
    const int tid  = threadIdx.x;
    const int wid  = tid >> 5;
    const int lane = tid & 31;
    const int wsub = wid & 3;         // consumer: token subtile (16 rows)
    const int h    = (wid >> 2) & 1;  // consumer: column half (4 block-rows)
    const int m0   = blockIdx.x * MT;
    const int brg  = blockIdx.y;      // 8-block-row group (0..15)

    int*      row_off = (int*)(smem + OFF_ROWOFF);
    int*      cnt     = (int*)(smem + OFF_CNT);
    uint32_t* ubc     = (uint32_t*)(smem + OFF_UBC);
    float*    bias_s  = (float*)(smem + OFF_BIAS);
    uint32_t* ents    = (uint32_t*)(smem + OFF_ENT);

    // ---- planning + mbarrier init ----
    if (tid < 9) row_off[tid] = lb(block_ids, N_BLK, (brg * NBR + tid) * IN_B);
    if (tid >= 16 && tid < 272) cnt[tid - 16] = 0;
    if (tid < GCOLS) bias_s[tid] = bias[brg * GCOLS + tid];
    if (tid == 0) {
        #pragma unroll
        for (int s = 0; s < NSTG; s++) {
            MBARRIER_INIT(sb + OFF_MBF + 8 * s, 32);    // full: 32 lanes of owner producer
            MBARRIER_INIT(sb + OFF_MBE + 8 * s, NCONS); // empty: 8 consumer warps
        }
    }
    __syncthreads();

    const int e0  = row_off[0];
    const int tot = row_off[NBR] - e0;

    for (int t = tid; t < tot; t += NTHR) {
        int flat = block_ids[e0 + t];
        int key = ((flat & 127) << 1) | (((flat >> 7) - brg * NBR) >> 2);
        atomicAdd(&cnt[key], 1);
    }
    __syncthreads();

    if (tid == 0) {
        int acc = 0, nuv = 0;
        for (int c = 0; c < 128; c++) {
            int c0 = cnt[2 * c], c1 = cnt[2 * c + 1];
            if (c0 + c1) ubc[nuv++] = ((uint32_t)c << 24) | ((uint32_t)acc << 8)
                                    | ((uint32_t)c0 << 4) | (uint32_t)c1;
            cnt[2 * c] = acc;
            cnt[2 * c + 1] = acc + c0;
            acc += c0 + c1;
        }
        *(int*)(smem + OFF_NU) = nuv;
    }
    __syncthreads();

    for (int t = tid; t < tot; t += NTHR) {
        int flat = block_ids[e0 + t];
        int bc   = flat & 127;
        int brl  = (flat >> 7) - brg * NBR;          // 0..7
        int pos  = atomicAdd(&cnt[(bc << 1) | (brl >> 2)], 1);
        ents[pos] = ((uint32_t)(e0 + t) << 8) | (uint32_t)brl;
    }
    __syncthreads();

    const int nu = *(int*)(smem + OFF_NU);

    if (wid >= PWID) {
        // ================= producer warps (2) =================
        const int pw = wid - PWID;    // 0 -> even iterations, 1 -> odd
        const __half*  x_src_lane = g_xh + (size_t)(m0 + (lane >> 2)) * IN_F + (lane & 3) * 8;
        const uint32_t x_dst_lane = (uint32_t)((lane >> 2) * 80 + (lane & 3) * 16);
        const uint32_t w_src_lane = (uint32_t)((lane >> 2) * 32 + (lane & 3) * 8);
        const uint32_t w_dst_lane = (uint32_t)((lane >> 2) * 80 + (lane & 3) * 16);

        int last = -1;
        for (int it = pw; it < nu; it += 2) {
            // publish my previous stage FIRST (earliest possible delivery):
            // at loop top my only outstanding group is iteration it-2.
            if (it >= 2) {
                CP_WAIT(0);
                MBARRIER_ARRIVE(sb + OFF_MBF + 8 * ((it - 2) & 3));
            }
            int s = it & 3;
            if (it >= 4) MBARRIER_WAIT_PARITY(sb + OFF_MBE + 8 * s, ((it >> 2) - 1) & 1);

            uint32_t u = ubc[it];
            int bc  = (int)(u >> 24);
            int st  = (int)((u >> 8) & 0xFFFF);
            int cct = (int)((u >> 4) & 15) + (int)(u & 15);
            uint32_t base = sb + OFF_STG + (uint32_t)s * STAGE;
            const __half* xs = x_src_lane + bc * 32;
            #pragma unroll
            for (int q = 0; q < 8; q++)
                cp16(base + x_dst_lane + (uint32_t)(q * 640), xs + (size_t)q * 8 * IN_F);
            uint32_t wbase = base + X_SZ;
            for (int e = 0; e < cct; e++) {
                const __half* wsrc = g_wh + (size_t)(ents[st + e] >> 8) * 1024 + w_src_lane;
                uint32_t wdst = wbase + (uint32_t)e * WBLK + w_dst_lane;
                #pragma unroll
                for (int kk = 0; kk < 4; kk++)
                    cp16(wdst + (uint32_t)(kk * 640), wsrc + kk * 256);
            }
            CP_COMMIT();
            last = it;
        }
        if (last >= 0) {
            CP_WAIT(0);
            MBARRIER_ARRIVE(sb + OFF_MBF + 8 * (last & 3));
        }
    } else {
        // ================= consumer warps =================
        const int jj = lane >> 3, rr = lane & 7;
        const uint32_t a_off = (uint32_t)((wsub * 16 + (jj & 1) * 8 + rr) * 80 + (jj >> 1) * 16);
        const uint32_t b_off = (uint32_t)(((jj >> 1) * 8 + rr) * 80 + (jj & 1) * 16);

        float acc[16][4];
        #pragma unroll
        for (int nt = 0; nt < 16; nt++)
            #pragma unroll
            for (int q = 0; q < 4; q++) acc[nt][q] = 0.0f;

        for (int i = 0; i < nu; i++) {
            int s = i & 3, k = i >> 2;

            // decode BEFORE the wait (ubc/ents are frozen after planning)
            uint32_t u = ubc[i];
            int st  = (int)((u >> 8) & 0xFFFF);
            int cc0 = (int)((u >> 4) & 15);
            int myst = st + (h ? cc0 : 0);
            int mycc = h ? (int)(u & 15) : cc0;

            if (mycc) {
                MBARRIER_WAIT_PARITY(sb + OFF_MBF + 8 * s, k & 1);
                uint32_t stg = sb + OFF_STG + (uint32_t)s * STAGE;
                uint32_t A[2][4];
                LDSM4(A[0][0], A[0][1], A[0][2], A[0][3], stg + a_off);
                LDSM4(A[1][0], A[1][1], A[1][2], A[1][3], stg + a_off + 32);
                uint32_t wslot0 = stg + X_SZ + (uint32_t)(myst - st) * WBLK + b_off;
                for (int e = 0; e < mycc; e++) {
                    uint32_t en = ents[myst + e];
                    uint32_t base = wslot0 + (uint32_t)e * WBLK;
                    switch (en & 3) {
                        case 0: do_block<0>(acc, A, base); break;
                        case 1: do_block<1>(acc, A, base); break;
                        case 2: do_block<2>(acc, A, base); break;
                        default: do_block<3>(acc, A, base); break;
                    }
                }
                __syncwarp();
            }
            // arrive empty regardless (skip-wait on empty iterations is safe:
            // we never touch the stage, so ordering vs producer refill holds)
            if (lane == 0) MBARRIER_ARRIVE(sb + OFF_MBE + 8 * s);
        }

        // ---- epilogue ----
        const int r4 = lane >> 2, c2 = (lane & 3) * 2;
        const int row = m0 + wsub * 16 + r4;
        const float* bs = bias_s + h * 128;
        #pragma unroll
        for (int nt = 0; nt < 16; nt++) {
            int lc = nt * 8 + c2;
            float b0 = bs[lc], b1 = bs[lc + 1];
            float* p = out + (size_t)row * OUT_F + brg * GCOLS + h * 128 + lc;
            float2 v0 = { acc[nt][0] + b0, acc[nt][1] + b1 };
            float2 v1 = { acc[nt][2] + b0, acc[nt][3] + b1 };
            *(float2*)p = v0;
            *(float2*)(p + 8 * OUT_F) = v1;
        }
    }
}

// ---------------- launch ----------------
extern "C" void kernel_launch(void* const* d_in, const int* in_sizes, int n_in,
                              void* d_out, int out_size)
{
    const float* x    = (const float*)d_in[0];   // [4096,4096] f32
    const float* w    = (const float*)d_in[1];   // [8192,32,32] f32
    const float* bias = (const float*)d_in[2];   // [4096] f32
    const int*   bids = (const int*)d_in[3];     // [8192] i32 sorted flat ids
    float* out = (float*)d_out;

    void* px = nullptr; void* pw = nullptr;
    cudaGetSymbolAddress(&px, g_xh);
    cudaGetSymbolAddress(&pw, g_wh);

    const int nx4 = (N_TOK * IN_F) / 4;
    const int nw4 = (N_BLK * 1024) / 4;
    cvt_f16_all<<<4096, 256>>>((const float4*)x, (uint2*)px,
                               (const float4*)w, (uint2*)pw, nx4, nx4 + nw4);

    cudaFuncSetAttribute(bsl_main, cudaFuncAttributeMaxDynamicSharedMemorySize, SMEM_TOTAL);
    bsl_main<<<dim3(64, 16), NTHR, SMEM_TOTAL>>>(bias, bids, out);

    (void)in_sizes; (void)n_in; (void)out_size;
}